// round 1
// baseline (speedup 1.0000x reference)
#include <cuda_runtime.h>

// Problem constants (fixed by setup_inputs)
constexpr int B  = 2;
constexpr int V  = 6;
constexpr int C  = 256;
constexpr int Q  = 900;
constexpr int KP = 4;
constexpr int H0 = 56, W0 = 100;
constexpr int H1 = 28, W1 = 50;

constexpr int L0_ELEMS = B * V * C * H0 * W0;   // 17,203,200
constexpr int L1_ELEMS = B * V * C * H1 * W1;   //  4,300,800

// Channel-last scratch: [B,V,H,W,C] for level 0 then level 1
__device__ float g_feat[L0_ELEMS + L1_ELEMS];

// ---------------------------------------------------------------------------
// Transpose [BV, C, HW] -> [BV, HW, C] (channel-last), tiled 32x32.
// ---------------------------------------------------------------------------
__global__ void transpose_k(const float* __restrict__ in, int outBase, int HW)
{
    __shared__ float tile[32][33];
    const int bv = blockIdx.z;
    const float* src = in + bv * C * HW;
    float* dst = g_feat + outBase + bv * HW * C;

    const int hw0 = blockIdx.x * 32;
    const int c0  = blockIdx.y * 32;
    const int tx = threadIdx.x, ty = threadIdx.y;

    const int hwL = hw0 + tx;
    if (hwL < HW) {
        #pragma unroll
        for (int j = ty; j < 32; j += 8)
            tile[j][tx] = src[(c0 + j) * HW + hwL];
    }
    __syncthreads();
    #pragma unroll
    for (int j = ty; j < 32; j += 8) {
        int hw = hw0 + j;
        if (hw < HW)
            dst[hw * C + c0 + tx] = tile[tx][j];
    }
}

// ---------------------------------------------------------------------------
// Main sampler: one block per (b,q). 256 threads.
//   Phase 1 (threads 0..47): 24 projections x 2 levels -> 192 tap records
//   Phase 2: 4 tap-groups x 64 channel-threads, float4 accumulate, smem reduce
// ---------------------------------------------------------------------------
__global__ __launch_bounds__(256) void sample_k(
    const float* __restrict__ refs,   // [B,Q,3]
    const float* __restrict__ intr,   // [B,V,3,3]
    const float* __restrict__ extr,   // [B,V,4,4]
    const float* __restrict__ kps,    // [KP,3]
    float* __restrict__ out)          // [B,Q,C]
{
    __shared__ int    s_off[192];
    __shared__ float  s_w[192];
    __shared__ int    s_valid[V * KP];   // 24
    __shared__ float4 s_part[3][64];

    const int bq = blockIdx.x;
    const int b  = bq / Q;
    const int tid = threadIdx.x;

    if (tid < 2 * V * KP) {              // 48 threads
        const int s      = tid;
        const int sample = s >> 1;       // 0..23  (v*KP + k)
        const int lev    = s & 1;
        const int v      = sample >> 2;
        const int k      = sample & 3;

        // point = refs[b,q] + keypoints[k]
        const float* r  = refs + bq * 3;
        const float* kp = kps + k * 3;
        const float px = r[0] + kp[0];
        const float py = r[1] + kp[1];
        const float pz = r[2] + kp[2];

        const float* E  = extr + (b * V + v) * 16;
        const float* Km = intr + (b * V + v) * 9;

        const float cx = E[0] * px + E[1] * py + E[2]  * pz + E[3];
        const float cy = E[4] * px + E[5] * py + E[6]  * pz + E[7];
        const float cz = E[8] * px + E[9] * py + E[10] * pz + E[11];

        const float u0 = Km[0] * cx + Km[1] * cy + Km[2] * cz;
        const float u1 = Km[3] * cx + Km[4] * cy + Km[5] * cz;
        const float z  = Km[6] * cx + Km[7] * cy + Km[8] * cz;

        const bool valid = (z > 0.0f);
        if (lev == 0) s_valid[sample] = valid ? 1 : 0;

        const int base4 = s * 4;
        if (!valid) {
            #pragma unroll
            for (int t = 0; t < 4; t++) { s_w[base4 + t] = 0.0f; s_off[base4 + t] = 0; }
        } else {
            const int H    = lev ? H1 : H0;
            const int W    = lev ? W1 : W0;
            const int base = (lev ? L0_ELEMS : 0) + (b * V + v) * H * W * C;

            const float zs = fmaxf(z, 1e-5f);
            float x = u0 / zs;
            float y = u1 / zs;
            // clamp to a safe window (values outside are fully OOB anyway)
            x = fminf(fmaxf(x, -2.0f), (float)(W + 2));
            y = fminf(fmaxf(y, -2.0f), (float)(H + 2));

            const float x0f = floorf(x), y0f = floorf(y);
            const int x0 = (int)x0f, y0 = (int)y0f;
            const float wx = x - x0f, wy = y - y0f;

            const float tw[4] = { (1.f - wx) * (1.f - wy), wx * (1.f - wy),
                                  (1.f - wx) * wy,          wx * wy };
            #pragma unroll
            for (int t = 0; t < 4; t++) {
                const int xi = x0 + (t & 1);
                const int yi = y0 + (t >> 1);
                const bool inb = (xi >= 0) & (xi < W) & (yi >= 0) & (yi < H);
                const int xc = min(max(xi, 0), W - 1);
                const int yc = min(max(yi, 0), H - 1);
                s_off[base4 + t] = base + (yc * W + xc) * C;
                s_w[base4 + t]   = inb ? tw[t] : 0.0f;
            }
        }
    }
    __syncthreads();

    // count valid samples (same for both levels)
    int cnt = 0;
    #pragma unroll
    for (int i = 0; i < V * KP; i++) cnt += s_valid[i];
    const float inv = 1.0f / (2.0f * fmaxf((float)cnt, 1.0f));

    const int g  = tid >> 6;    // tap group 0..3
    const int ln = tid & 63;    // channel-group (float4) 0..63

    float4 acc = make_float4(0.f, 0.f, 0.f, 0.f);
    for (int t = g; t < 192; t += 4) {
        const float wt = s_w[t];           // warp-uniform
        if (wt != 0.0f) {
            const float4 fv = ((const float4*)(g_feat + s_off[t]))[ln];
            acc.x += wt * fv.x;
            acc.y += wt * fv.y;
            acc.z += wt * fv.z;
            acc.w += wt * fv.w;
        }
    }

    if (g > 0) s_part[g - 1][ln] = acc;
    __syncthreads();

    if (g == 0) {
        #pragma unroll
        for (int i = 0; i < 3; i++) {
            const float4 p = s_part[i][ln];
            acc.x += p.x; acc.y += p.y; acc.z += p.z; acc.w += p.w;
        }
        acc.x *= inv; acc.y *= inv; acc.z *= inv; acc.w *= inv;
        ((float4*)(out + bq * C))[ln] = acc;
    }
}

extern "C" void kernel_launch(void* const* d_in, const int* in_sizes, int n_in,
                              void* d_out, int out_size)
{
    const float* f8   = (const float*)d_in[0];
    const float* f16  = (const float*)d_in[1];
    const float* refs = (const float*)d_in[2];
    const float* intr = (const float*)d_in[3];
    const float* extr = (const float*)d_in[4];
    const float* kps  = (const float*)d_in[5];
    float* out = (float*)d_out;

    // Level 0: HW = 5600 -> 175 tiles; Level 1: HW = 1400 -> 44 tiles
    dim3 tb(32, 8);
    transpose_k<<<dim3((H0 * W0 + 31) / 32, C / 32, B * V), tb>>>(f8, 0, H0 * W0);
    transpose_k<<<dim3((H1 * W1 + 31) / 32, C / 32, B * V), tb>>>(f16, L0_ELEMS, H1 * W1);

    sample_k<<<B * Q, 256>>>(refs, intr, extr, kps, out);
    (void)in_sizes; (void)n_in; (void)out_size;
}

// round 2
// speedup vs baseline: 1.3583x; 1.3583x over previous
#include <cuda_runtime.h>

// Problem constants (fixed by setup_inputs)
constexpr int B  = 2;
constexpr int V  = 6;
constexpr int C  = 256;
constexpr int Q  = 900;
constexpr int KP = 4;
constexpr int H0 = 56, W0 = 100;
constexpr int H1 = 28, W1 = 50;

constexpr int L0_ELEMS = B * V * C * H0 * W0;   // 17,203,200
constexpr int L1_ELEMS = B * V * C * H1 * W1;   //  4,300,800

// Channel-last scratch: [B,V,H,W,C] for level 0 then level 1
__device__ float g_feat[L0_ELEMS + L1_ELEMS];

// ---------------------------------------------------------------------------
// Transpose [BV, C, HW] -> [BV, HW, C], float4 on both global sides.
// Tile = 32 hw x 32 c, 256 threads, scalar smem (stride 33, conflict-free).
// ---------------------------------------------------------------------------
__global__ __launch_bounds__(256) void transpose_k(
    const float* __restrict__ in, int outBase, int HW)
{
    __shared__ float tile[32][33];   // [hw_local][c_local]
    const int bv = blockIdx.z;
    const float* src = in + (size_t)bv * C * HW;
    float* dst = g_feat + outBase + (size_t)bv * HW * C;

    const int hw0 = blockIdx.x * 32;
    const int c0  = blockIdx.y * 32;
    const int tid = threadIdx.x;

    // Load phase: tx = float4-slot along hw (0..7), ty = channel (0..31)
    {
        const int tx = tid & 7;
        const int ty = tid >> 3;
        const int hw = hw0 + tx * 4;
        if (hw < HW) {
            const float4 f = *(const float4*)(src + (size_t)(c0 + ty) * HW + hw);
            tile[tx * 4 + 0][ty] = f.x;
            tile[tx * 4 + 1][ty] = f.y;
            tile[tx * 4 + 2][ty] = f.z;
            tile[tx * 4 + 3][ty] = f.w;
        }
    }
    __syncthreads();

    // Store phase: txc = float4-slot along c (0..7), tyh = hw (0..31)
    {
        const int txc = tid & 7;
        const int tyh = tid >> 3;
        const int hw  = hw0 + tyh;
        if (hw < HW) {
            float4 f;
            f.x = tile[tyh][txc * 4 + 0];
            f.y = tile[tyh][txc * 4 + 1];
            f.z = tile[tyh][txc * 4 + 2];
            f.w = tile[tyh][txc * 4 + 3];
            *(float4*)(dst + (size_t)hw * C + c0 + txc * 4) = f;
        }
    }
}

// ---------------------------------------------------------------------------
// Main sampler: one block per (b,q). 256 threads.
//   Phase 1 (threads 0..47): 24 projections x 2 levels -> 192 tap records
//   Phase 2: 4 tap-groups x 64 channel-threads, float4 accumulate, smem reduce
// ---------------------------------------------------------------------------
__global__ __launch_bounds__(256) void sample_k(
    const float* __restrict__ refs,   // [B,Q,3]
    const float* __restrict__ intr,   // [B,V,3,3]
    const float* __restrict__ extr,   // [B,V,4,4]
    const float* __restrict__ kps,    // [KP,3]
    float* __restrict__ out)          // [B,Q,C]
{
    __shared__ int    s_off[192];
    __shared__ float  s_w[192];
    __shared__ int    s_valid[V * KP];   // 24
    __shared__ float4 s_part[3][64];

    const int bq = blockIdx.x;
    const int b  = bq / Q;
    const int tid = threadIdx.x;

    if (tid < 2 * V * KP) {              // 48 threads
        const int s      = tid;
        const int sample = s >> 1;       // 0..23  (v*KP + k)
        const int lev    = s & 1;
        const int v      = sample >> 2;
        const int k      = sample & 3;

        // point = refs[b,q] + keypoints[k]
        const float* r  = refs + bq * 3;
        const float* kp = kps + k * 3;
        const float px = r[0] + kp[0];
        const float py = r[1] + kp[1];
        const float pz = r[2] + kp[2];

        const float* E  = extr + (b * V + v) * 16;
        const float* Km = intr + (b * V + v) * 9;

        const float cx = E[0] * px + E[1] * py + E[2]  * pz + E[3];
        const float cy = E[4] * px + E[5] * py + E[6]  * pz + E[7];
        const float cz = E[8] * px + E[9] * py + E[10] * pz + E[11];

        const float u0 = Km[0] * cx + Km[1] * cy + Km[2] * cz;
        const float u1 = Km[3] * cx + Km[4] * cy + Km[5] * cz;
        const float z  = Km[6] * cx + Km[7] * cy + Km[8] * cz;

        const bool valid = (z > 0.0f);
        if (lev == 0) s_valid[sample] = valid ? 1 : 0;

        const int base4 = s * 4;
        if (!valid) {
            #pragma unroll
            for (int t = 0; t < 4; t++) { s_w[base4 + t] = 0.0f; s_off[base4 + t] = 0; }
        } else {
            const int H    = lev ? H1 : H0;
            const int W    = lev ? W1 : W0;
            const int base = (lev ? L0_ELEMS : 0) + (b * V + v) * H * W * C;

            const float zs = fmaxf(z, 1e-5f);
            float x = u0 / zs;
            float y = u1 / zs;
            // clamp to a safe window (values outside are fully OOB anyway)
            x = fminf(fmaxf(x, -2.0f), (float)(W + 2));
            y = fminf(fmaxf(y, -2.0f), (float)(H + 2));

            const float x0f = floorf(x), y0f = floorf(y);
            const int x0 = (int)x0f, y0 = (int)y0f;
            const float wx = x - x0f, wy = y - y0f;

            const float tw[4] = { (1.f - wx) * (1.f - wy), wx * (1.f - wy),
                                  (1.f - wx) * wy,          wx * wy };
            #pragma unroll
            for (int t = 0; t < 4; t++) {
                const int xi = x0 + (t & 1);
                const int yi = y0 + (t >> 1);
                const bool inb = (xi >= 0) & (xi < W) & (yi >= 0) & (yi < H);
                const int xc = min(max(xi, 0), W - 1);
                const int yc = min(max(yi, 0), H - 1);
                s_off[base4 + t] = base + (yc * W + xc) * C;
                s_w[base4 + t]   = inb ? tw[t] : 0.0f;
            }
        }
    }
    __syncthreads();

    // count valid samples (same for both levels)
    int cnt = 0;
    #pragma unroll
    for (int i = 0; i < V * KP; i++) cnt += s_valid[i];
    const float inv = 1.0f / (2.0f * fmaxf((float)cnt, 1.0f));

    const int g  = tid >> 6;    // tap group 0..3
    const int ln = tid & 63;    // channel-group (float4) 0..63

    float4 acc = make_float4(0.f, 0.f, 0.f, 0.f);
    for (int t = g; t < 192; t += 4) {
        const float wt = s_w[t];           // warp-uniform
        if (wt != 0.0f) {
            const float4 fv = ((const float4*)(g_feat + s_off[t]))[ln];
            acc.x += wt * fv.x;
            acc.y += wt * fv.y;
            acc.z += wt * fv.z;
            acc.w += wt * fv.w;
        }
    }

    if (g > 0) s_part[g - 1][ln] = acc;
    __syncthreads();

    if (g == 0) {
        #pragma unroll
        for (int i = 0; i < 3; i++) {
            const float4 p = s_part[i][ln];
            acc.x += p.x; acc.y += p.y; acc.z += p.z; acc.w += p.w;
        }
        acc.x *= inv; acc.y *= inv; acc.z *= inv; acc.w *= inv;
        ((float4*)(out + bq * C))[ln] = acc;
    }
}

extern "C" void kernel_launch(void* const* d_in, const int* in_sizes, int n_in,
                              void* d_out, int out_size)
{
    const float* f8   = (const float*)d_in[0];
    const float* f16  = (const float*)d_in[1];
    const float* refs = (const float*)d_in[2];
    const float* intr = (const float*)d_in[3];
    const float* extr = (const float*)d_in[4];
    const float* kps  = (const float*)d_in[5];
    float* out = (float*)d_out;

    transpose_k<<<dim3((H0 * W0 + 31) / 32, C / 32, B * V), 256>>>(f8, 0, H0 * W0);
    transpose_k<<<dim3((H1 * W1 + 31) / 32, C / 32, B * V), 256>>>(f16, L0_ELEMS, H1 * W1);

    sample_k<<<B * Q, 256>>>(refs, intr, extr, kps, out);
    (void)in_sizes; (void)n_in; (void)out_size;
}

// round 3
// speedup vs baseline: 1.5565x; 1.1459x over previous
#include <cuda_runtime.h>

// Problem constants (fixed by setup_inputs)
constexpr int B  = 2;
constexpr int V  = 6;
constexpr int C  = 256;
constexpr int Q  = 900;
constexpr int KP = 4;
constexpr int H0 = 56, W0 = 100;
constexpr int H1 = 28, W1 = 50;

constexpr int HW0 = H0 * W0;   // 5600
constexpr int HW1 = H1 * W1;   // 1400

constexpr int L0_ELEMS = B * V * C * HW0;   // 17,203,200
constexpr int L1_ELEMS = B * V * C * HW1;   //  4,300,800

// Channel-last scratch: [B,V,H,W,C] for level 0 then level 1
__device__ float g_feat[L0_ELEMS + L1_ELEMS];

// ---------------------------------------------------------------------------
// Fused transpose [BV, C, HW] -> [BV, HW, C] for both levels.
// Tile = 64 hw x 64 c, 256 threads, 4 independent float4 LDG/STG per thread
// (MLP=4 per phase). blockIdx.x selects level + hw tile.
// ---------------------------------------------------------------------------
constexpr int T0 = (HW0 + 63) / 64;   // 88 hw tiles for level 0
constexpr int T1 = (HW1 + 63) / 64;   // 22 hw tiles for level 1

__global__ __launch_bounds__(256) void transpose_fused_k(
    const float* __restrict__ f8, const float* __restrict__ f16)
{
    __shared__ float tile[64][65];   // [hw_local][c_local]

    const int bx = blockIdx.x;
    const float* src;
    float* dst;
    int HW, hw0;
    if (bx < T0) { src = f8;  dst = g_feat;            HW = HW0; hw0 = bx * 64; }
    else         { src = f16; dst = g_feat + L0_ELEMS; HW = HW1; hw0 = (bx - T0) * 64; }

    const int bv = blockIdx.z;
    const int c0 = blockIdx.y * 64;
    src += (size_t)bv * C * HW;
    dst += (size_t)bv * HW * C;
    const int tid = threadIdx.x;

    // Load phase: 1024 float4 tasks (16 hw-slots x 64 channels), 4 per thread.
    // Warp: 16 consecutive slots over 2 channel rows -> 256 B coalesced runs.
    #pragma unroll
    for (int i = 0; i < 4; i++) {
        const int task = tid + i * 256;
        const int slot = task & 15;       // hw float4 slot (0..15)
        const int cc   = task >> 4;       // channel within tile (0..63)
        const int hw   = hw0 + slot * 4;
        if (hw < HW) {                    // HW % 4 == 0, float4-safe
            const float4 f = *(const float4*)(src + (size_t)(c0 + cc) * HW + hw);
            tile[slot * 4 + 0][cc] = f.x;
            tile[slot * 4 + 1][cc] = f.y;
            tile[slot * 4 + 2][cc] = f.z;
            tile[slot * 4 + 3][cc] = f.w;
        }
    }
    __syncthreads();

    // Store phase: 1024 float4 tasks (64 hw x 16 c-slots), 4 per thread.
    // Warp: 16 consecutive c-slots over 2 hw rows -> 256 B coalesced runs.
    #pragma unroll
    for (int i = 0; i < 4; i++) {
        const int task  = tid + i * 256;
        const int cslot = task & 15;      // c float4 slot (0..15)
        const int hw    = task >> 4;      // hw within tile (0..63)
        const int hwg   = hw0 + hw;
        if (hwg < HW) {
            float4 f;
            f.x = tile[hw][cslot * 4 + 0];
            f.y = tile[hw][cslot * 4 + 1];
            f.z = tile[hw][cslot * 4 + 2];
            f.w = tile[hw][cslot * 4 + 3];
            *(float4*)(dst + (size_t)hwg * C + c0 + cslot * 4) = f;
        }
    }
}

// ---------------------------------------------------------------------------
// Main sampler: one block per (b,q). 256 threads.
//   Phase 1 (threads 0..47): 24 projections x 2 levels -> 192 tap records
//   Phase 2: 4 tap-groups x 64 channel-threads, float4 accumulate, smem reduce
// ---------------------------------------------------------------------------
__global__ __launch_bounds__(256) void sample_k(
    const float* __restrict__ refs,   // [B,Q,3]
    const float* __restrict__ intr,   // [B,V,3,3]
    const float* __restrict__ extr,   // [B,V,4,4]
    const float* __restrict__ kps,    // [KP,3]
    float* __restrict__ out)          // [B,Q,C]
{
    __shared__ int    s_off[192];
    __shared__ float  s_w[192];
    __shared__ int    s_valid[V * KP];   // 24
    __shared__ float4 s_part[3][64];

    const int bq = blockIdx.x;
    const int b  = bq / Q;
    const int tid = threadIdx.x;

    if (tid < 2 * V * KP) {              // 48 threads
        const int s      = tid;
        const int sample = s >> 1;       // 0..23  (v*KP + k)
        const int lev    = s & 1;
        const int v      = sample >> 2;
        const int k      = sample & 3;

        // point = refs[b,q] + keypoints[k]
        const float* r  = refs + bq * 3;
        const float* kp = kps + k * 3;
        const float px = r[0] + kp[0];
        const float py = r[1] + kp[1];
        const float pz = r[2] + kp[2];

        const float* E  = extr + (b * V + v) * 16;
        const float* Km = intr + (b * V + v) * 9;

        const float cx = E[0] * px + E[1] * py + E[2]  * pz + E[3];
        const float cy = E[4] * px + E[5] * py + E[6]  * pz + E[7];
        const float cz = E[8] * px + E[9] * py + E[10] * pz + E[11];

        const float u0 = Km[0] * cx + Km[1] * cy + Km[2] * cz;
        const float u1 = Km[3] * cx + Km[4] * cy + Km[5] * cz;
        const float z  = Km[6] * cx + Km[7] * cy + Km[8] * cz;

        const bool valid = (z > 0.0f);
        if (lev == 0) s_valid[sample] = valid ? 1 : 0;

        const int base4 = s * 4;
        if (!valid) {
            #pragma unroll
            for (int t = 0; t < 4; t++) { s_w[base4 + t] = 0.0f; s_off[base4 + t] = 0; }
        } else {
            const int H    = lev ? H1 : H0;
            const int W    = lev ? W1 : W0;
            const int base = (lev ? L0_ELEMS : 0) + (b * V + v) * H * W * C;

            const float zs = fmaxf(z, 1e-5f);
            float x = u0 / zs;
            float y = u1 / zs;
            // clamp to a safe window (values outside are fully OOB anyway)
            x = fminf(fmaxf(x, -2.0f), (float)(W + 2));
            y = fminf(fmaxf(y, -2.0f), (float)(H + 2));

            const float x0f = floorf(x), y0f = floorf(y);
            const int x0 = (int)x0f, y0 = (int)y0f;
            const float wx = x - x0f, wy = y - y0f;

            const float tw[4] = { (1.f - wx) * (1.f - wy), wx * (1.f - wy),
                                  (1.f - wx) * wy,          wx * wy };
            #pragma unroll
            for (int t = 0; t < 4; t++) {
                const int xi = x0 + (t & 1);
                const int yi = y0 + (t >> 1);
                const bool inb = (xi >= 0) & (xi < W) & (yi >= 0) & (yi < H);
                const int xc = min(max(xi, 0), W - 1);
                const int yc = min(max(yi, 0), H - 1);
                s_off[base4 + t] = base + (yc * W + xc) * C;
                s_w[base4 + t]   = inb ? tw[t] : 0.0f;
            }
        }
    }
    __syncthreads();

    // count valid samples (same for both levels)
    int cnt = 0;
    #pragma unroll
    for (int i = 0; i < V * KP; i++) cnt += s_valid[i];
    const float inv = 1.0f / (2.0f * fmaxf((float)cnt, 1.0f));

    const int g  = tid >> 6;    // tap group 0..3
    const int ln = tid & 63;    // channel-group (float4) 0..63

    float4 acc = make_float4(0.f, 0.f, 0.f, 0.f);
    for (int t = g; t < 192; t += 4) {
        const float wt = s_w[t];           // warp-uniform
        if (wt != 0.0f) {
            const float4 fv = ((const float4*)(g_feat + s_off[t]))[ln];
            acc.x += wt * fv.x;
            acc.y += wt * fv.y;
            acc.z += wt * fv.z;
            acc.w += wt * fv.w;
        }
    }

    if (g > 0) s_part[g - 1][ln] = acc;
    __syncthreads();

    if (g == 0) {
        #pragma unroll
        for (int i = 0; i < 3; i++) {
            const float4 p = s_part[i][ln];
            acc.x += p.x; acc.y += p.y; acc.z += p.z; acc.w += p.w;
        }
        acc.x *= inv; acc.y *= inv; acc.z *= inv; acc.w *= inv;
        ((float4*)(out + bq * C))[ln] = acc;
    }
}

extern "C" void kernel_launch(void* const* d_in, const int* in_sizes, int n_in,
                              void* d_out, int out_size)
{
    const float* f8   = (const float*)d_in[0];
    const float* f16  = (const float*)d_in[1];
    const float* refs = (const float*)d_in[2];
    const float* intr = (const float*)d_in[3];
    const float* extr = (const float*)d_in[4];
    const float* kps  = (const float*)d_in[5];
    float* out = (float*)d_out;

    transpose_fused_k<<<dim3(T0 + T1, C / 64, B * V), 256>>>(f8, f16);
    sample_k<<<B * Q, 256>>>(refs, intr, extr, kps, out);
    (void)in_sizes; (void)n_in; (void)out_size;
}

// round 4
// speedup vs baseline: 2.0000x; 1.2849x over previous
#include <cuda_runtime.h>
#include <cuda_fp16.h>

// Problem constants (fixed by setup_inputs)
constexpr int B  = 2;
constexpr int V  = 6;
constexpr int C  = 256;
constexpr int Q  = 900;
constexpr int KP = 4;
constexpr int H0 = 56, W0 = 100;
constexpr int H1 = 28, W1 = 50;

constexpr int HW0 = H0 * W0;   // 5600
constexpr int HW1 = H1 * W1;   // 1400

constexpr int L0_ELEMS = B * V * C * HW0;   // 17,203,200
constexpr int L1_ELEMS = B * V * C * HW1;   //  4,300,800

// Channel-last fp16 scratch: [B,V,H,W,C] level 0 then level 1 (~43 MB)
__device__ __half g_feat_h[L0_ELEMS + L1_ELEMS];

// ---------------------------------------------------------------------------
// Fused transpose [BV, C, HW] (fp32) -> [BV, HW, C] (fp16), both levels.
// Tile = 64 hw x 64 c, 256 threads, 4 independent float4 LDGs / 4 uint2 STGs
// per thread (MLP=4 per phase).
// ---------------------------------------------------------------------------
constexpr int T0 = (HW0 + 63) / 64;   // 88 hw tiles for level 0
constexpr int T1 = (HW1 + 63) / 64;   // 22 hw tiles for level 1

__global__ __launch_bounds__(256) void transpose_fused_k(
    const float* __restrict__ f8, const float* __restrict__ f16)
{
    __shared__ float tile[64][65];   // [hw_local][c_local]

    const int bx = blockIdx.x;
    const float* src;
    __half* dst;
    int HW, hw0;
    if (bx < T0) { src = f8;  dst = g_feat_h;            HW = HW0; hw0 = bx * 64; }
    else         { src = f16; dst = g_feat_h + L0_ELEMS; HW = HW1; hw0 = (bx - T0) * 64; }

    const int bv = blockIdx.z;
    const int c0 = blockIdx.y * 64;
    src += (size_t)bv * C * HW;
    dst += (size_t)bv * HW * C;
    const int tid = threadIdx.x;

    // Load phase: 1024 float4 tasks (16 hw-slots x 64 channels), 4 per thread.
    #pragma unroll
    for (int i = 0; i < 4; i++) {
        const int task = tid + i * 256;
        const int slot = task & 15;       // hw float4 slot (0..15)
        const int cc   = task >> 4;       // channel within tile (0..63)
        const int hw   = hw0 + slot * 4;
        if (hw < HW) {                    // HW % 4 == 0, float4-safe
            const float4 f = *(const float4*)(src + (size_t)(c0 + cc) * HW + hw);
            tile[slot * 4 + 0][cc] = f.x;
            tile[slot * 4 + 1][cc] = f.y;
            tile[slot * 4 + 2][cc] = f.z;
            tile[slot * 4 + 3][cc] = f.w;
        }
    }
    __syncthreads();

    // Store phase: 1024 half4 tasks (64 hw x 16 c-slots), 4 per thread.
    #pragma unroll
    for (int i = 0; i < 4; i++) {
        const int task  = tid + i * 256;
        const int cslot = task & 15;      // c half4 slot (0..15)
        const int hw    = task >> 4;      // hw within tile (0..63)
        const int hwg   = hw0 + hw;
        if (hwg < HW) {
            const __half2 h01 = __floats2half2_rn(tile[hw][cslot * 4 + 0],
                                                  tile[hw][cslot * 4 + 1]);
            const __half2 h23 = __floats2half2_rn(tile[hw][cslot * 4 + 2],
                                                  tile[hw][cslot * 4 + 3]);
            uint2 u;
            u.x = *(const unsigned int*)&h01;
            u.y = *(const unsigned int*)&h23;
            *(uint2*)(dst + (size_t)hwg * C + c0 + cslot * 4) = u;
        }
    }
}

// ---------------------------------------------------------------------------
// Main sampler: one block per (b,q), 256 threads.
//   Phase 1: 192 threads (one per tap) project + compute tap weight, then a
//            deterministic ballot/prefix compaction of live (w!=0) taps.
//   Phase 2: 8 warp-groups x 32 lanes x 8 channels, uint4 (8-half) gathers
//            over only the live taps; fp32 accumulate; smem reduce.
// ---------------------------------------------------------------------------
__global__ __launch_bounds__(256) void sample_k(
    const float* __restrict__ refs,   // [B,Q,3]
    const float* __restrict__ intr,   // [B,V,3,3]
    const float* __restrict__ extr,   // [B,V,4,4]
    const float* __restrict__ kps,    // [KP,3]
    float* __restrict__ out)          // [B,Q,C]
{
    __shared__ float s_cw[192];
    __shared__ int   s_coff[192];
    __shared__ int   s_warpcnt[6];
    __shared__ int   s_valid[V * KP];         // 24
    __shared__ float s_part[7][32][8];

    const int bq  = blockIdx.x;
    const int b   = bq / Q;
    const int tid = threadIdx.x;
    const int wid = tid >> 5;
    const int ln5 = tid & 31;

    bool  live = false;
    float wgt  = 0.0f;
    int   off  = 0;

    if (tid < 192) {
        const int s      = tid >> 2;     // 0..47
        const int t      = tid & 3;      // tap 0..3
        const int lev    = s & 1;
        const int sample = s >> 1;       // 0..23
        const int v      = sample >> 2;
        const int k      = sample & 3;

        const float* r  = refs + bq * 3;
        const float* kp = kps + k * 3;
        const float px = r[0] + kp[0];
        const float py = r[1] + kp[1];
        const float pz = r[2] + kp[2];

        const float* E  = extr + (b * V + v) * 16;
        const float* Km = intr + (b * V + v) * 9;

        const float cx = E[0] * px + E[1] * py + E[2]  * pz + E[3];
        const float cy = E[4] * px + E[5] * py + E[6]  * pz + E[7];
        const float cz = E[8] * px + E[9] * py + E[10] * pz + E[11];

        const float u0 = Km[0] * cx + Km[1] * cy + Km[2] * cz;
        const float u1 = Km[3] * cx + Km[4] * cy + Km[5] * cz;
        const float z  = Km[6] * cx + Km[7] * cy + Km[8] * cz;

        const bool valid = (z > 0.0f);
        if (lev == 0 && t == 0) s_valid[sample] = valid ? 1 : 0;

        if (valid) {
            const int H    = lev ? H1 : H0;
            const int W    = lev ? W1 : W0;
            const int base = (lev ? L0_ELEMS : 0) + (b * V + v) * H * W * C;

            const float zs = fmaxf(z, 1e-5f);
            float x = u0 / zs;
            float y = u1 / zs;
            x = fminf(fmaxf(x, -2.0f), (float)(W + 2));
            y = fminf(fmaxf(y, -2.0f), (float)(H + 2));

            const float x0f = floorf(x), y0f = floorf(y);
            const int x0 = (int)x0f, y0 = (int)y0f;
            const float wx = x - x0f, wy = y - y0f;

            const float fx = (t & 1) ? wx : (1.0f - wx);
            const float fy = (t >> 1) ? wy : (1.0f - wy);

            const int xi = x0 + (t & 1);
            const int yi = y0 + (t >> 1);
            const bool inb = (xi >= 0) & (xi < W) & (yi >= 0) & (yi < H);
            if (inb) {
                wgt = fx * fy;
                off = base + (yi * W + xi) * C;
                live = (wgt != 0.0f);
            }
        }
    }

    // Deterministic warp-level compaction (order-preserving)
    const unsigned mask = __ballot_sync(0xffffffffu, live);
    if (wid < 6 && ln5 == 0) s_warpcnt[wid] = __popc(mask);
    __syncthreads();

    int nTaps = 0;
    int base6 = 0;
    #pragma unroll
    for (int i = 0; i < 6; i++) {
        const int c6 = s_warpcnt[i];
        if (i < wid) base6 += c6;
        nTaps += c6;
    }
    if (live) {
        const int idx = base6 + __popc(mask & ((1u << ln5) - 1u));
        s_cw[idx]   = wgt;
        s_coff[idx] = off;
    }

    int cnt = 0;
    #pragma unroll
    for (int i = 0; i < V * KP; i++) cnt += s_valid[i];
    const float inv = 1.0f / (2.0f * fmaxf((float)cnt, 1.0f));
    __syncthreads();

    // Phase 2: gather over live taps only.
    const int g  = wid;    // tap group 0..7 (one warp each)
    const int ln = ln5;    // 8-channel slot 0..31

    float acc[8];
    #pragma unroll
    for (int j = 0; j < 8; j++) acc[j] = 0.0f;

    for (int t = g; t < nTaps; t += 8) {
        const float wt = s_cw[t];                         // warp-uniform
        const uint4 qv = ((const uint4*)(g_feat_h + s_coff[t]))[ln];
        const float2 f0 = __half22float2(*(const __half2*)&qv.x);
        const float2 f1 = __half22float2(*(const __half2*)&qv.y);
        const float2 f2 = __half22float2(*(const __half2*)&qv.z);
        const float2 f3 = __half22float2(*(const __half2*)&qv.w);
        acc[0] += wt * f0.x;  acc[1] += wt * f0.y;
        acc[2] += wt * f1.x;  acc[3] += wt * f1.y;
        acc[4] += wt * f2.x;  acc[5] += wt * f2.y;
        acc[6] += wt * f3.x;  acc[7] += wt * f3.y;
    }

    if (g > 0) {
        #pragma unroll
        for (int j = 0; j < 8; j++) s_part[g - 1][ln][j] = acc[j];
    }
    __syncthreads();

    if (g == 0) {
        #pragma unroll
        for (int i = 0; i < 7; i++)
            #pragma unroll
            for (int j = 0; j < 8; j++) acc[j] += s_part[i][ln][j];

        float4 o0, o1;
        o0.x = acc[0] * inv; o0.y = acc[1] * inv;
        o0.z = acc[2] * inv; o0.w = acc[3] * inv;
        o1.x = acc[4] * inv; o1.y = acc[5] * inv;
        o1.z = acc[6] * inv; o1.w = acc[7] * inv;
        float4* op = (float4*)(out + (size_t)bq * C) + ln * 2;
        op[0] = o0;
        op[1] = o1;
    }
}

extern "C" void kernel_launch(void* const* d_in, const int* in_sizes, int n_in,
                              void* d_out, int out_size)
{
    const float* f8   = (const float*)d_in[0];
    const float* f16  = (const float*)d_in[1];
    const float* refs = (const float*)d_in[2];
    const float* intr = (const float*)d_in[3];
    const float* extr = (const float*)d_in[4];
    const float* kps  = (const float*)d_in[5];
    float* out = (float*)d_out;

    transpose_fused_k<<<dim3(T0 + T1, C / 64, B * V), 256>>>(f8, f16);
    sample_k<<<B * Q, 256>>>(refs, intr, extr, kps, out);
    (void)in_sizes; (void)n_in; (void)out_size;
}

// round 5
// speedup vs baseline: 3.3171x; 1.6585x over previous
#include <cuda_runtime.h>
#include <cuda_fp16.h>

// Problem constants (fixed by setup_inputs)
constexpr int B  = 2;
constexpr int V  = 6;
constexpr int C  = 256;
constexpr int Q  = 900;
constexpr int KP = 4;
constexpr int H0 = 56, W0 = 100;
constexpr int H1 = 28, W1 = 50;

constexpr int HW0 = H0 * W0;   // 5600
constexpr int HW1 = H1 * W1;   // 1400

constexpr int L0_ELEMS = B * V * C * HW0;   // 17,203,200
constexpr int L1_ELEMS = B * V * C * HW1;   //  4,300,800

constexpr int T0 = (HW0 + 63) / 64;   // 88 hw tiles (level 0)
constexpr int T1 = (HW1 + 63) / 64;   // 22 hw tiles (level 1)
constexpr int NTILE = T0 + T1;        // 110
constexpr int BV = B * V;             // 12

// Channel-last fp16 scratch: [B,V,H,W,C] level 0 then level 1 (~43 MB)
__device__ __half g_feat_h[L0_ELEMS + L1_ELEMS];
// Per-(tile,bv) touch flags
__device__ int    g_touch[NTILE * BV];
// Compact tap lists per query: {w (float bits), offset}
__device__ uint2  g_taps[B * Q * 192];
__device__ int    g_ntaps[B * Q];
__device__ float  g_inv[B * Q];

// ---------------------------------------------------------------------------
__global__ void zero_k()
{
    for (int i = threadIdx.x; i < NTILE * BV; i += blockDim.x) g_touch[i] = 0;
}

// ---------------------------------------------------------------------------
// Projection + compaction: one block per (b,q), 192 threads (one per tap).
// Writes compact tap list + inv to global, marks touched transpose tiles.
// ---------------------------------------------------------------------------
__global__ __launch_bounds__(192) void proj_k(
    const float* __restrict__ refs,   // [B,Q,3]
    const float* __restrict__ intr,   // [B,V,3,3]
    const float* __restrict__ extr,   // [B,V,4,4]
    const float* __restrict__ kps)    // [KP,3]
{
    __shared__ int s_warpcnt[6];
    __shared__ int s_valid[V * KP];   // 24

    const int bq  = blockIdx.x;
    const int b   = bq / Q;
    const int tid = threadIdx.x;
    const int wid = tid >> 5;
    const int ln5 = tid & 31;

    bool  live = false;
    float wgt  = 0.0f;
    int   off  = 0;
    int   tileIdx = 0;

    {
        const int s      = tid >> 2;     // 0..47
        const int t      = tid & 3;      // corner 0..3
        const int lev    = s & 1;
        const int sample = s >> 1;       // 0..23
        const int v      = sample >> 2;
        const int k      = sample & 3;

        const float* r  = refs + bq * 3;
        const float* kp = kps + k * 3;
        const float px = r[0] + kp[0];
        const float py = r[1] + kp[1];
        const float pz = r[2] + kp[2];

        const float* E  = extr + (b * V + v) * 16;
        const float* Km = intr + (b * V + v) * 9;

        const float cx = E[0] * px + E[1] * py + E[2]  * pz + E[3];
        const float cy = E[4] * px + E[5] * py + E[6]  * pz + E[7];
        const float cz = E[8] * px + E[9] * py + E[10] * pz + E[11];

        const float u0 = Km[0] * cx + Km[1] * cy + Km[2] * cz;
        const float u1 = Km[3] * cx + Km[4] * cy + Km[5] * cz;
        const float z  = Km[6] * cx + Km[7] * cy + Km[8] * cz;

        const bool valid = (z > 0.0f);
        if (lev == 0 && t == 0) s_valid[sample] = valid ? 1 : 0;

        if (valid) {
            const int H    = lev ? H1 : H0;
            const int W    = lev ? W1 : W0;
            const int bvg  = b * V + v;
            const int base = (lev ? L0_ELEMS : 0) + bvg * H * W * C;

            const float zs = fmaxf(z, 1e-5f);
            float x = u0 / zs;
            float y = u1 / zs;
            x = fminf(fmaxf(x, -2.0f), (float)(W + 2));
            y = fminf(fmaxf(y, -2.0f), (float)(H + 2));

            const float x0f = floorf(x), y0f = floorf(y);
            const int x0 = (int)x0f, y0 = (int)y0f;
            const float wx = x - x0f, wy = y - y0f;

            const float fx = (t & 1) ? wx : (1.0f - wx);
            const float fy = (t >> 1) ? wy : (1.0f - wy);

            const int xi = x0 + (t & 1);
            const int yi = y0 + (t >> 1);
            const bool inb = (xi >= 0) & (xi < W) & (yi >= 0) & (yi < H);
            if (inb) {
                const int hw = yi * W + xi;
                wgt = fx * fy;
                off = base + hw * C;
                live = (wgt != 0.0f);
                const int tile = (lev ? T0 : 0) + (hw >> 6);
                tileIdx = tile * BV + bvg;
            }
        }
    }

    // Deterministic order-preserving compaction across the 6 warps
    const unsigned mask = __ballot_sync(0xffffffffu, live);
    if (ln5 == 0) s_warpcnt[wid] = __popc(mask);
    __syncthreads();

    int nTaps = 0, base6 = 0;
    #pragma unroll
    for (int i = 0; i < 6; i++) {
        const int c6 = s_warpcnt[i];
        if (i < wid) base6 += c6;
        nTaps += c6;
    }
    if (live) {
        const int idx = base6 + __popc(mask & ((1u << ln5) - 1u));
        g_taps[bq * 192 + idx] = make_uint2(__float_as_uint(wgt), (unsigned)off);
        g_touch[tileIdx] = 1;    // racing 1-writes are benign
    }

    if (tid == 0) {
        int cnt = 0;
        #pragma unroll
        for (int i = 0; i < V * KP; i++) cnt += s_valid[i];
        g_ntaps[bq] = nTaps;
        g_inv[bq]   = 1.0f / (2.0f * fmaxf((float)cnt, 1.0f));
    }
}

// ---------------------------------------------------------------------------
// Fused transpose [BV, C, HW] (fp32) -> [BV, HW, C] (fp16), both levels,
// skipping tiles never touched by any tap.
// ---------------------------------------------------------------------------
__global__ __launch_bounds__(256) void transpose_fused_k(
    const float* __restrict__ f8, const float* __restrict__ f16)
{
    __shared__ float tile[64][65];   // [hw_local][c_local]

    const int bx = blockIdx.x;
    const int bv = blockIdx.z;
    if (g_touch[bx * BV + bv] == 0) return;   // uniform early-out

    const float* src;
    __half* dst;
    int HW, hw0;
    if (bx < T0) { src = f8;  dst = g_feat_h;            HW = HW0; hw0 = bx * 64; }
    else         { src = f16; dst = g_feat_h + L0_ELEMS; HW = HW1; hw0 = (bx - T0) * 64; }

    const int c0 = blockIdx.y * 64;
    src += (size_t)bv * C * HW;
    dst += (size_t)bv * HW * C;
    const int tid = threadIdx.x;

    // Load phase: 1024 float4 tasks (16 hw-slots x 64 channels), 4 per thread.
    #pragma unroll
    for (int i = 0; i < 4; i++) {
        const int task = tid + i * 256;
        const int slot = task & 15;       // hw float4 slot (0..15)
        const int cc   = task >> 4;       // channel within tile (0..63)
        const int hw   = hw0 + slot * 4;
        if (hw < HW) {                    // HW % 4 == 0, float4-safe
            const float4 f = *(const float4*)(src + (size_t)(c0 + cc) * HW + hw);
            tile[slot * 4 + 0][cc] = f.x;
            tile[slot * 4 + 1][cc] = f.y;
            tile[slot * 4 + 2][cc] = f.z;
            tile[slot * 4 + 3][cc] = f.w;
        }
    }
    __syncthreads();

    // Store phase: 1024 half4 tasks (64 hw x 16 c-slots), 4 per thread.
    #pragma unroll
    for (int i = 0; i < 4; i++) {
        const int task  = tid + i * 256;
        const int cslot = task & 15;      // c half4 slot (0..15)
        const int hw    = task >> 4;      // hw within tile (0..63)
        const int hwg   = hw0 + hw;
        if (hwg < HW) {
            const __half2 h01 = __floats2half2_rn(tile[hw][cslot * 4 + 0],
                                                  tile[hw][cslot * 4 + 1]);
            const __half2 h23 = __floats2half2_rn(tile[hw][cslot * 4 + 2],
                                                  tile[hw][cslot * 4 + 3]);
            uint2 u;
            u.x = *(const unsigned int*)&h01;
            u.y = *(const unsigned int*)&h23;
            *(uint2*)(dst + (size_t)hwg * C + c0 + cslot * 4) = u;
        }
    }
}

// ---------------------------------------------------------------------------
// Gather kernel: one block per (b,q), 256 threads. Tap list precomputed.
//   8 warps x 32 lanes x 8 channels, uint4 (8-half) gathers; fp32 accumulate.
// ---------------------------------------------------------------------------
__global__ __launch_bounds__(256) void sample_k(float* __restrict__ out)
{
    __shared__ uint2 s_tap[192];
    __shared__ float s_part[7][32][8];

    const int bq  = blockIdx.x;
    const int tid = threadIdx.x;
    const int g   = tid >> 5;   // warp / tap group 0..7
    const int ln  = tid & 31;   // 8-channel slot 0..31

    const int nTaps = g_ntaps[bq];
    if (tid < nTaps) s_tap[tid] = g_taps[bq * 192 + tid];
    __syncthreads();

    float acc[8];
    #pragma unroll
    for (int j = 0; j < 8; j++) acc[j] = 0.0f;

    for (int t = g; t < nTaps; t += 8) {
        const uint2 tap = s_tap[t];                       // warp-uniform
        const float wt  = __uint_as_float(tap.x);
        const uint4 qv  = ((const uint4*)(g_feat_h + (int)tap.y))[ln];
        const float2 f0 = __half22float2(*(const __half2*)&qv.x);
        const float2 f1 = __half22float2(*(const __half2*)&qv.y);
        const float2 f2 = __half22float2(*(const __half2*)&qv.z);
        const float2 f3 = __half22float2(*(const __half2*)&qv.w);
        acc[0] += wt * f0.x;  acc[1] += wt * f0.y;
        acc[2] += wt * f1.x;  acc[3] += wt * f1.y;
        acc[4] += wt * f2.x;  acc[5] += wt * f2.y;
        acc[6] += wt * f3.x;  acc[7] += wt * f3.y;
    }

    if (g > 0) {
        #pragma unroll
        for (int j = 0; j < 8; j++) s_part[g - 1][ln][j] = acc[j];
    }
    __syncthreads();

    if (g == 0) {
        const float inv = g_inv[bq];
        #pragma unroll
        for (int i = 0; i < 7; i++)
            #pragma unroll
            for (int j = 0; j < 8; j++) acc[j] += s_part[i][ln][j];

        float4 o0, o1;
        o0.x = acc[0] * inv; o0.y = acc[1] * inv;
        o0.z = acc[2] * inv; o0.w = acc[3] * inv;
        o1.x = acc[4] * inv; o1.y = acc[5] * inv;
        o1.z = acc[6] * inv; o1.w = acc[7] * inv;
        float4* op = (float4*)(out + (size_t)bq * C) + ln * 2;
        op[0] = o0;
        op[1] = o1;
    }
}

extern "C" void kernel_launch(void* const* d_in, const int* in_sizes, int n_in,
                              void* d_out, int out_size)
{
    const float* f8   = (const float*)d_in[0];
    const float* f16  = (const float*)d_in[1];
    const float* refs = (const float*)d_in[2];
    const float* intr = (const float*)d_in[3];
    const float* extr = (const float*)d_in[4];
    const float* kps  = (const float*)d_in[5];
    float* out = (float*)d_out;

    zero_k<<<1, 256>>>();
    proj_k<<<B * Q, 192>>>(refs, intr, extr, kps);
    transpose_fused_k<<<dim3(NTILE, C / 64, BV), 256>>>(f8, f16);
    sample_k<<<B * Q, 256>>>(out);
    (void)in_sizes; (void)n_in; (void)out_size;
}